// round 2
// baseline (speedup 1.0000x reference)
#include <cuda_runtime.h>

#define BATCH   16
#define NPTS    4096
#define TILE    1024
#define THREADS 256
#define PPT     4            // 4 x-points per thread = 2 packed pairs
#define NPAIR   (PPT / 2)

__device__ double g_acc[2];

__global__ void zero_acc_kernel() {
    if (threadIdx.x < 2) g_acc[threadIdx.x] = 0.0;
}

__device__ __forceinline__ unsigned long long pack2(float lo, float hi) {
    float2 f = make_float2(lo, hi);
    return *reinterpret_cast<unsigned long long*>(&f);
}

__global__ __launch_bounds__(THREADS) void chamfer_kernel(
    const float* __restrict__ xyz1, const float* __restrict__ xyz2)
{
    const int dir = blockIdx.z;
    const float* __restrict__ xs = (dir == 0) ? xyz1 : xyz2;
    const float* __restrict__ ys = (dir == 0) ? xyz2 : xyz1;
    const int b    = blockIdx.y;
    const int base = blockIdx.x * (THREADS * PPT);
    const int tid  = threadIdx.x;

    // Pre-duplicated candidate tiles: A = (-2x,-2x,-2y,-2y), B = (-2z,-2z,sq,sq)
    __shared__ float4 tileA[TILE];
    __shared__ float4 tileB[TILE];

    // Load this thread's x-points, pack pairs into f32x2 operands.
    unsigned long long xq[NPAIR], yq[NPAIR], zq[NPAIR];
    float mn[PPT], sq1sum = 0.0f;
#pragma unroll
    for (int q = 0; q < NPAIR; q++) {
        int n0 = base + tid + (2 * q + 0) * THREADS;
        int n1 = base + tid + (2 * q + 1) * THREADS;
        const float* p0 = xs + ((size_t)b * NPTS + n0) * 3;
        const float* p1 = xs + ((size_t)b * NPTS + n1) * 3;
        float a0 = p0[0], b0 = p0[1], c0 = p0[2];
        float a1 = p1[0], b1 = p1[1], c1 = p1[2];
        xq[q] = pack2(a0, a1);
        yq[q] = pack2(b0, b1);
        zq[q] = pack2(c0, c1);
        sq1sum += a0 * a0 + b0 * b0 + c0 * c0;
        sq1sum += a1 * a1 + b1 * b1 + c1 * c1;
        mn[2 * q + 0] = 3.4e38f;
        mn[2 * q + 1] = 3.4e38f;
    }

    for (int t0 = 0; t0 < NPTS; t0 += TILE) {
        __syncthreads();
#pragma unroll
        for (int j = 0; j < TILE / THREADS; j++) {
            int ml = tid + j * THREADS;
            int m  = t0 + ml;
            const float* yp = ys + ((size_t)b * NPTS + m) * 3;
            float a = yp[0], c = yp[1], d = yp[2];
            float na = -2.0f * a, nc = -2.0f * c, nd = -2.0f * d;
            float sq = a * a + c * c + d * d;
            tileA[ml] = make_float4(na, na, nc, nc);
            tileB[ml] = make_float4(nd, nd, sq, sq);
        }
        __syncthreads();

#pragma unroll 4
        for (int i = 0; i < TILE; i++) {
            // LDS.128 broadcast: packed (cvx,cvx),(cvy,cvy) / (cvz,cvz),(sq,sq)
            ulonglong2 A  = *reinterpret_cast<const ulonglong2*>(&tileA[i]);
            ulonglong2 Bv = *reinterpret_cast<const ulonglong2*>(&tileB[i]);
#pragma unroll
            for (int q = 0; q < NPAIR; q++) {
                unsigned long long t;
                asm("fma.rn.f32x2 %0, %1, %2, %3;"
                    : "=l"(t) : "l"(zq[q]), "l"(Bv.x), "l"(Bv.y));
                asm("fma.rn.f32x2 %0, %1, %2, %0;"
                    : "+l"(t) : "l"(yq[q]), "l"(A.y));
                asm("fma.rn.f32x2 %0, %1, %2, %0;"
                    : "+l"(t) : "l"(xq[q]), "l"(A.x));
                float2 tf = *reinterpret_cast<float2*>(&t);
                mn[2 * q + 0] = fminf(mn[2 * q + 0], tf.x);
                mn[2 * q + 1] = fminf(mn[2 * q + 1], tf.y);
            }
        }
    }

    // Per-thread sum of final distances (||x||^2 added once at the end).
    float s = sq1sum;
#pragma unroll
    for (int p = 0; p < PPT; p++) s += mn[p];

    // Block reduction: warp shuffle + smem + one atomic per block.
    __shared__ float red[THREADS / 32];
#pragma unroll
    for (int o = 16; o > 0; o >>= 1) s += __shfl_down_sync(0xffffffffu, s, o);
    if ((tid & 31) == 0) red[tid >> 5] = s;
    __syncthreads();
    if (tid < THREADS / 32) {
        s = red[tid];
#pragma unroll
        for (int o = (THREADS / 64); o > 0; o >>= 1)
            s += __shfl_down_sync(0xffu, s, o);
        if (tid == 0) atomicAdd(&g_acc[dir], (double)s);
    }
}

__global__ void finalize_kernel(float* out) {
    if (threadIdx.x < 2)
        out[threadIdx.x] = (float)(g_acc[threadIdx.x] / (double)(BATCH * NPTS));
}

extern "C" void kernel_launch(void* const* d_in, const int* in_sizes, int n_in,
                              void* d_out, int out_size)
{
    const float* xyz1 = (const float*)d_in[0];
    const float* xyz2 = (const float*)d_in[1];
    float* out = (float*)d_out;

    zero_acc_kernel<<<1, 32>>>();
    dim3 grid(NPTS / (THREADS * PPT), BATCH, 2);   // (4, 16, 2) = 128 blocks
    chamfer_kernel<<<grid, THREADS>>>(xyz1, xyz2);
    finalize_kernel<<<1, 32>>>(out);
}

// round 3
// speedup vs baseline: 1.3689x; 1.3689x over previous
#include <cuda_runtime.h>

#define BATCH   16
#define NPTS    4096
#define SPLIT   8
#define CTILE   (NPTS / SPLIT)   // 512 candidates per block
#define THREADS 256
#define PPT     4                // 1024 x-points per block

__device__ double       g_acc[2];
__device__ unsigned int g_min[2 * BATCH * NPTS];   // monotone-encoded fp32 mins

// ---- monotone float<->uint map (atomicMin-compatible for any sign) ----
__device__ __forceinline__ unsigned int enc_f(float f) {
    unsigned int u = __float_as_uint(f);
    return (u & 0x80000000u) ? ~u : (u | 0x80000000u);
}
__device__ __forceinline__ float dec_f(unsigned int k) {
    unsigned int u = (k & 0x80000000u) ? (k & 0x7FFFFFFFu) : ~k;
    return __uint_as_float(u);
}

__global__ void init_kernel() {
    if (blockIdx.x == 0 && threadIdx.x < 2) g_acc[threadIdx.x] = 0.0;
    int total = 2 * BATCH * NPTS;
    for (int i = blockIdx.x * blockDim.x + threadIdx.x; i < total;
         i += gridDim.x * blockDim.x)
        g_min[i] = 0xFFFFFFFFu;
}

__global__ __launch_bounds__(THREADS) void chamfer_kernel(
    const float* __restrict__ xyz1, const float* __restrict__ xyz2)
{
    const int dir   = blockIdx.z >> 3;          // 0 or 1
    const int split = blockIdx.z & 7;           // candidate sub-range
    const float* __restrict__ xs = (dir == 0) ? xyz1 : xyz2;
    const float* __restrict__ ys = (dir == 0) ? xyz2 : xyz1;
    const int b    = blockIdx.y;
    const int base = blockIdx.x * (THREADS * PPT);
    const int tid  = threadIdx.x;

    __shared__ float4 tile[CTILE];              // (-2y.x, -2y.y, -2y.z, ||y||^2)

    // Register-resident x-points.
    float x0[PPT], x1[PPT], x2[PPT], mn[PPT], sq1[PPT];
#pragma unroll
    for (int p = 0; p < PPT; p++) {
        int n = base + tid + p * THREADS;
        const float* xp = xs + ((size_t)b * NPTS + n) * 3;
        x0[p] = xp[0]; x1[p] = xp[1]; x2[p] = xp[2];
        sq1[p] = x0[p] * x0[p] + x1[p] * x1[p] + x2[p] * x2[p];
        mn[p]  = 3.4e38f;
    }

    // Stage this block's candidate sub-range once.
    {
        int c0 = split * CTILE;
#pragma unroll
        for (int j = 0; j < CTILE / THREADS; j++) {
            int ml = tid + j * THREADS;
            const float* yp = ys + ((size_t)b * NPTS + c0 + ml) * 3;
            float a = yp[0], c = yp[1], d = yp[2];
            tile[ml] = make_float4(-2.0f * a, -2.0f * c, -2.0f * d,
                                   a * a + c * c + d * d);
        }
    }
    __syncthreads();

#pragma unroll 4
    for (int i = 0; i < CTILE; i++) {
        float4 cv = tile[i];                    // warp-broadcast, conflict-free
#pragma unroll
        for (int p = 0; p < PPT; p++) {
            float t = fmaf(x0[p], cv.x,
                      fmaf(x1[p], cv.y,
                      fmaf(x2[p], cv.z, cv.w)));
            mn[p] = fminf(mn[p], t);
        }
    }

    // Combine partial mins across candidate-splits (constant sq1 offset per
    // point commutes with min over splits).
    unsigned int* row = g_min + ((dir * BATCH + b) << 12);
#pragma unroll
    for (int p = 0; p < PPT; p++) {
        int n = base + tid + p * THREADS;
        atomicMin(&row[n], enc_f(mn[p] + sq1[p]));
    }
}

__global__ __launch_bounds__(THREADS) void reduce_kernel() {
    const int row = blockIdx.x;                 // 0..31 = dir*16 + b
    const int dir = row >> 4;
    const unsigned int* src = g_min + (row << 12);
    const int tid = threadIdx.x;

    float s = 0.0f;
#pragma unroll
    for (int j = 0; j < NPTS / THREADS; j++)
        s += dec_f(src[tid + j * THREADS]);

    __shared__ float red[THREADS / 32];
#pragma unroll
    for (int o = 16; o > 0; o >>= 1) s += __shfl_down_sync(0xffffffffu, s, o);
    if ((tid & 31) == 0) red[tid >> 5] = s;
    __syncthreads();
    if (tid < THREADS / 32) {
        s = red[tid];
#pragma unroll
        for (int o = (THREADS / 64); o > 0; o >>= 1)
            s += __shfl_down_sync(0xffu, s, o);
        if (tid == 0) atomicAdd(&g_acc[dir], (double)s);
    }
}

__global__ void finalize_kernel(float* out) {
    if (threadIdx.x < 2)
        out[threadIdx.x] = (float)(g_acc[threadIdx.x] / (double)(BATCH * NPTS));
}

extern "C" void kernel_launch(void* const* d_in, const int* in_sizes, int n_in,
                              void* d_out, int out_size)
{
    const float* xyz1 = (const float*)d_in[0];
    const float* xyz2 = (const float*)d_in[1];
    float* out = (float*)d_out;

    init_kernel<<<128, 256>>>();
    dim3 grid(NPTS / (THREADS * PPT), BATCH, 2 * SPLIT);   // (4, 16, 16) = 1024 blocks
    chamfer_kernel<<<grid, THREADS>>>(xyz1, xyz2);
    reduce_kernel<<<2 * BATCH, THREADS>>>();
    finalize_kernel<<<1, 32>>>(out);
}